// round 3
// baseline (speedup 1.0000x reference)
#include <cuda_runtime.h>
#include <cuda_bf16.h>
#include <stdint.h>

#define T_STEPS 16
#define BATCH   8192

// Output offsets (floats): output_seq, hc1_final, hc2, hc3, hc4, i2h_seq, h2h_seq
#define O_OUTSEQ 0ul
#define O_HC1F   1048576ul
#define O_HC2    3145728ul
#define O_HC3    5242880ul
#define O_HC4    7340032ul
#define O_I2H    9437184ul
#define O_H2H    42991616ul

__device__ float g_wh2h_r[256 * 256];   // W_h2h pre-rounded to tf32

__device__ __forceinline__ float f2tff(float x) {
    uint32_t u; asm("cvt.rna.tf32.f32 %0, %1;" : "=r"(u) : "f"(x));
    return __uint_as_float(u);
}
__device__ __forceinline__ float my_tanh(float x) {
    float e = __expf(2.f * x);
    return 1.f - __fdividef(2.f, e + 1.f);
}
__device__ __forceinline__ void mma8(float c[4], const uint32_t a[4],
                                     uint32_t b0, uint32_t b1) {
    asm volatile(
        "mma.sync.aligned.m16n8k8.row.col.f32.tf32.tf32.f32 "
        "{%0,%1,%2,%3}, {%4,%5,%6,%7}, {%8,%9}, {%0,%1,%2,%3};\n"
        : "+f"(c[0]), "+f"(c[1]), "+f"(c[2]), "+f"(c[3])
        : "r"(a[0]), "r"(a[1]), "r"(a[2]), "r"(a[3]), "r"(b0), "r"(b1));
}
__device__ __forceinline__ void cpa16(uint32_t dst, const void* src) {
    asm volatile("cp.async.cg.shared.global [%0], [%1], 16;" :: "r"(dst), "l"(src) : "memory");
}

// ---------------- kernel 0: round W_h2h ----------------
__global__ void k_round_w(const float* __restrict__ W) {
    int i = blockIdx.x * 256 + threadIdx.x;
    g_wh2h_r[i] = f2tff(W[i]);
}

// ---------------- kernel 1: i2h_seq --------------------
#define XS 68   // 68 % 32 == 4 -> conflict-free fragment loads

__global__ void __launch_bounds__(256, 2) k_i2h(
    const float* __restrict__ x, const float* __restrict__ Wi,
    const float* __restrict__ bi, float* __restrict__ out)
{
    extern __shared__ float sm[];
    float* xs = sm;              // [64][68]
    float* ws = sm + 64 * XS;    // [256][68]
    float* bs = ws + 256 * XS;   // [256]

    const int tid = threadIdx.x;
    const long rb = (long)blockIdx.x * 64;

    for (int i = tid; i < 64 * 64; i += 256) {
        int r = i >> 6, c = i & 63;
        xs[r * XS + c] = x[(rb + r) * 64 + c];
    }
    for (int i = tid; i < 256 * 64; i += 256) {
        int r = i >> 6, c = i & 63;
        ws[r * XS + c] = f2tff(Wi[i]);
    }
    bs[tid] = bi[tid];
    __syncthreads();

    const int wid = tid >> 5, lane = tid & 31;
    const int g = lane >> 2, tg = lane & 3;
    const int mg = wid & 1, ng = wid >> 1;

    float acc[2][8][4];
#pragma unroll
    for (int a = 0; a < 2; a++)
#pragma unroll
        for (int b = 0; b < 8; b++)
#pragma unroll
            for (int c = 0; c < 4; c++) acc[a][b][c] = 0.f;

#pragma unroll
    for (int k0 = 0; k0 < 64; k0 += 8) {
        uint32_t af[2][4];
#pragma unroll
        for (int mt = 0; mt < 2; mt++) {
            const float* p = xs + (mg * 32 + mt * 16 + g) * XS + k0;
            af[mt][0] = __float_as_uint(p[tg]);
            af[mt][1] = __float_as_uint(p[8 * XS + tg]);
            af[mt][2] = __float_as_uint(p[tg + 4]);
            af[mt][3] = __float_as_uint(p[8 * XS + tg + 4]);
        }
#pragma unroll
        for (int nt = 0; nt < 8; nt++) {
            const float* q = ws + (ng * 64 + nt * 8 + g) * XS + k0;
            uint32_t b0 = __float_as_uint(q[tg]);
            uint32_t b1 = __float_as_uint(q[tg + 4]);
            mma8(acc[0][nt], af[0], b0, b1);
            mma8(acc[1][nt], af[1], b0, b1);
        }
    }

#pragma unroll
    for (int mt = 0; mt < 2; mt++)
#pragma unroll
        for (int nt = 0; nt < 8; nt++) {
            int lr = mg * 32 + mt * 16 + g;
            int lc = ng * 64 + nt * 8 + 2 * tg;
            *(float2*)(out + O_I2H + (rb + lr) * 256 + lc) =
                make_float2(acc[mt][nt][0] + bs[lc], acc[mt][nt][1] + bs[lc + 1]);
            *(float2*)(out + O_I2H + (rb + lr + 8) * 256 + lc) =
                make_float2(acc[mt][nt][2] + bs[lc], acc[mt][nt][3] + bs[lc + 1]);
        }
}

// ---------------- kernel 2: recurrence + head ----------
#define HSS 260
#define WCS 36
#define WOS 260
#define O1S 65

__global__ void __launch_bounds__(256, 1) k_rnn(
    const float* __restrict__ hc1,  const float* __restrict__ bh2h,
    const float* __restrict__ Wh2o, const float* __restrict__ bh2o,
    const float* __restrict__ Wfcc, const float* __restrict__ bfcc,
    float* __restrict__ out)
{
    extern __shared__ float sm[];
    float* hs = sm;                   // [64][260]  h state (full fp32)
    float* wc = hs + 64 * HSS;        // [2][256][36] W_h2h chunk double-buffer
    float* wo = wc + 2 * 256 * WCS;   // [64][260]  W_h2o
    float* o1 = wo + 64 * WOS;        // [64][65]
    float* bh = o1 + 64 * O1S;        // 256
    float* bo = bh + 256;             // 64
    float* wf = bo + 64;              // 512
    float* bf = wf + 512;             // 8

    const int  tid = threadIdx.x;
    const long rb  = (long)blockIdx.x * 64;

    for (int i = tid; i < 64 * 256; i += 256) {
        int r = i >> 8, c = i & 255;
        hs[r * HSS + c] = hc1[(rb + r) * 256 + c];
        wo[r * HSS + c] = f2tff(Wh2o[i]);   // HSS == WOS
    }
    bh[tid] = bh2h[tid];
    if (tid < 64)  bo[tid] = bh2o[tid];
    if (tid < 8)   bf[tid] = bfcc[tid];
    for (int i = tid; i < 512; i += 256) wf[i] = Wfcc[i];
    __syncthreads();

    const int wid = tid >> 5, lane = tid & 31;
    const int g = lane >> 2, tg = lane & 3;
    const int mg = wid & 1, ng = wid >> 1;
    const uint32_t wc_base = (uint32_t)__cvta_generic_to_shared(wc);

    for (int t = 0; t < T_STEPS; t++) {
        float acc[2][8][4];
#pragma unroll
        for (int a = 0; a < 2; a++)
#pragma unroll
            for (int b = 0; b < 8; b++)
#pragma unroll
                for (int c = 0; c < 4; c++) acc[a][b][c] = 0.f;

        // prefetch chunk 0 into buffer 0
#pragma unroll
        for (int v = 0; v < 8; v++) {
            int i4 = tid + v * 256;
            int n = i4 >> 3, k4 = (i4 & 7) << 2;
            cpa16(wc_base + (uint32_t)((n * WCS + k4) * 4), g_wh2h_r + n * 256 + k4);
        }
        asm volatile("cp.async.commit_group;" ::: "memory");

        for (int ch = 0; ch < 8; ch++) {
            if (ch < 7) {
                int buf = (ch + 1) & 1;
#pragma unroll
                for (int v = 0; v < 8; v++) {
                    int i4 = tid + v * 256;
                    int n = i4 >> 3, k4 = (i4 & 7) << 2;
                    cpa16(wc_base + (uint32_t)((buf * 256 * WCS + n * WCS + k4) * 4),
                          g_wh2h_r + n * 256 + (ch + 1) * 32 + k4);
                }
                asm volatile("cp.async.commit_group;" ::: "memory");
                asm volatile("cp.async.wait_group 1;" ::: "memory");
            } else {
                asm volatile("cp.async.wait_group 0;" ::: "memory");
            }
            __syncthreads();

            const float* wcb = wc + (ch & 1) * 256 * WCS;
#pragma unroll
            for (int ki = 0; ki < 4; ki++) {
                int k0 = ch * 32 + ki * 8;
                int kl = ki * 8;
                uint32_t af[2][4];
#pragma unroll
                for (int mt = 0; mt < 2; mt++) {
                    const float* p = hs + (mg * 32 + mt * 16 + g) * HSS + k0;
                    af[mt][0] = __float_as_uint(p[tg]);
                    af[mt][1] = __float_as_uint(p[8 * HSS + tg]);
                    af[mt][2] = __float_as_uint(p[tg + 4]);
                    af[mt][3] = __float_as_uint(p[8 * HSS + tg + 4]);
                }
#pragma unroll
                for (int nt = 0; nt < 8; nt++) {
                    const float* q = wcb + (ng * 64 + nt * 8 + g) * WCS + kl;
                    uint32_t b0 = __float_as_uint(q[tg]);
                    uint32_t b1 = __float_as_uint(q[tg + 4]);
                    mma8(acc[0][nt], af[0], b0, b1);
                    mma8(acc[1][nt], af[1], b0, b1);
                }
            }
            __syncthreads();   // guard buffer reuse
        }

        // epilogue: h2h write, i2h read, tanh -> new h
        const size_t tb = (size_t)t * BATCH;
#pragma unroll
        for (int mt = 0; mt < 2; mt++)
#pragma unroll
            for (int nt = 0; nt < 8; nt++) {
                int lr = mg * 32 + mt * 16 + g;
                int lc = ng * 64 + nt * 8 + 2 * tg;
                size_t idx0 = (tb + rb + lr) * 256 + lc;
                size_t idx1 = idx0 + 8 * 256;
                float h0 = acc[mt][nt][0] + bh[lc];
                float h1 = acc[mt][nt][1] + bh[lc + 1];
                float h2 = acc[mt][nt][2] + bh[lc];
                float h3 = acc[mt][nt][3] + bh[lc + 1];
                *(float2*)(out + O_H2H + idx0) = make_float2(h0, h1);
                *(float2*)(out + O_H2H + idx1) = make_float2(h2, h3);
                float2 i0 = *(const float2*)(out + O_I2H + idx0);
                float2 i1 = *(const float2*)(out + O_I2H + idx1);
                hs[lr * HSS + lc]           = my_tanh(h0 + i0.x);
                hs[lr * HSS + lc + 1]       = my_tanh(h1 + i0.y);
                hs[(lr + 8) * HSS + lc]     = my_tanh(h2 + i1.x);
                hs[(lr + 8) * HSS + lc + 1] = my_tanh(h3 + i1.y);
            }
        __syncthreads();

        // head GEMM: [64 x 64], K=256; warps 2(m) x 4(n16)
        float ha[2][2][4];
#pragma unroll
        for (int a = 0; a < 2; a++)
#pragma unroll
            for (int b = 0; b < 2; b++)
#pragma unroll
                for (int c = 0; c < 4; c++) ha[a][b][c] = 0.f;
#pragma unroll
        for (int k0 = 0; k0 < 256; k0 += 8) {
            uint32_t af[2][4];
#pragma unroll
            for (int mt = 0; mt < 2; mt++) {
                const float* p = hs + (mg * 32 + mt * 16 + g) * HSS + k0;
                af[mt][0] = __float_as_uint(p[tg]);
                af[mt][1] = __float_as_uint(p[8 * HSS + tg]);
                af[mt][2] = __float_as_uint(p[tg + 4]);
                af[mt][3] = __float_as_uint(p[8 * HSS + tg + 4]);
            }
#pragma unroll
            for (int nt = 0; nt < 2; nt++) {
                const float* q = wo + (ng * 16 + nt * 8 + g) * WOS + k0;
                uint32_t b0 = __float_as_uint(q[tg]);
                uint32_t b1 = __float_as_uint(q[tg + 4]);
                mma8(ha[0][nt], af[0], b0, b1);
                mma8(ha[1][nt], af[1], b0, b1);
            }
        }
#pragma unroll
        for (int mt = 0; mt < 2; mt++)
#pragma unroll
            for (int nt = 0; nt < 2; nt++) {
                int lr = mg * 32 + mt * 16 + g;
                int lc = ng * 16 + nt * 8 + 2 * tg;
                o1[lr * O1S + lc]           = my_tanh(ha[mt][nt][0] + bo[lc]);
                o1[lr * O1S + lc + 1]       = my_tanh(ha[mt][nt][1] + bo[lc + 1]);
                o1[(lr + 8) * O1S + lc]     = my_tanh(ha[mt][nt][2] + bo[lc]);
                o1[(lr + 8) * O1S + lc + 1] = my_tanh(ha[mt][nt][3] + bo[lc + 1]);
            }
        __syncthreads();

        // fcc: [64,8] = o1[64,64] @ Wfcc^T + bfcc (SIMT, tiny)
        {
            int m = tid & 63, cp = tid >> 6;
            float s0 = bf[2 * cp], s1 = bf[2 * cp + 1];
            const float* orow = o1 + m * O1S;
            const float* w0 = wf + (2 * cp) * 64;
            const float* w1 = w0 + 64;
#pragma unroll
            for (int o = 0; o < 64; o++) {
                float v = orow[o];
                s0 = fmaf(v, w0[o], s0);
                s1 = fmaf(v, w1[o], s1);
            }
            float* dst = out + O_OUTSEQ + (tb + rb + m) * 8 + 2 * cp;
            dst[0] = s0;
            dst[1] = s1;
        }
        // next iteration's first __syncthreads (in ch loop) guards o1/hs reuse
    }

    // hc1_final
    for (int i = tid; i < 64 * 256; i += 256) {
        int r = i >> 8, c = i & 255;
        out[O_HC1F + (rb + r) * 256 + c] = hs[r * HSS + c];
    }
}

#define SM_I2H ((64 * XS + 256 * XS + 256) * 4)
#define SM_RNN ((64 * HSS + 2 * 256 * WCS + 64 * WOS + 64 * O1S + 256 + 64 + 512 + 8) * 4)

extern "C" void kernel_launch(void* const* d_in, const int* in_sizes, int n_in,
                              void* d_out, int out_size) {
    const float* x    = (const float*)d_in[0];
    const float* hc1  = (const float*)d_in[2];
    const float* hc2  = (const float*)d_in[3];
    const float* hc3  = (const float*)d_in[4];
    const float* hc4  = (const float*)d_in[5];
    const float* Wi2h = (const float*)d_in[6];
    const float* bi2h = (const float*)d_in[7];
    const float* Wh2h = (const float*)d_in[8];
    const float* bh2h = (const float*)d_in[9];
    const float* Wh2o = (const float*)d_in[10];
    const float* bh2o = (const float*)d_in[11];
    const float* Wfcc = (const float*)d_in[12];
    const float* bfcc = (const float*)d_in[13];
    float* out = (float*)d_out;

    cudaFuncSetAttribute(k_i2h, cudaFuncAttributeMaxDynamicSharedMemorySize, SM_I2H);
    cudaFuncSetAttribute(k_rnn, cudaFuncAttributeMaxDynamicSharedMemorySize, SM_RNN);

    k_round_w<<<256, 256>>>(Wh2h);
    k_i2h<<<(T_STEPS * BATCH) / 64, 256, SM_I2H>>>(x, Wi2h, bi2h, out);
    k_rnn<<<BATCH / 64, 256, SM_RNN>>>(hc1, bh2h, Wh2o, bh2o, Wfcc, bfcc, out);

    size_t hb = (size_t)BATCH * 256 * sizeof(float);
    cudaMemcpyAsync(out + O_HC2, hc2, hb, cudaMemcpyDeviceToDevice, 0);
    cudaMemcpyAsync(out + O_HC3, hc3, hb, cudaMemcpyDeviceToDevice, 0);
    cudaMemcpyAsync(out + O_HC4, hc4, hb, cudaMemcpyDeviceToDevice, 0);
}

// round 5
// speedup vs baseline: 1.3010x; 1.3010x over previous
#include <cuda_runtime.h>
#include <cuda_fp16.h>
#include <cuda_bf16.h>
#include <stdint.h>

#define T_STEPS 16
#define BATCH   8192

// Output offsets (floats): output_seq, hc1_final, hc2, hc3, hc4, i2h_seq, h2h_seq
#define O_OUTSEQ 0ul
#define O_HC1F   1048576ul
#define O_HC2    3145728ul
#define O_HC3    5242880ul
#define O_HC4    7340032ul
#define O_I2H    9437184ul
#define O_H2H    42991616ul

__device__ __forceinline__ float my_tanh(float x) {
    float e = __expf(2.f * x);
    return 1.f - __fdividef(2.f, e + 1.f);
}
__device__ __forceinline__ void mma16(float c[4], const uint32_t a[4],
                                      uint32_t b0, uint32_t b1) {
    asm volatile(
        "mma.sync.aligned.m16n8k16.row.col.f32.f16.f16.f32 "
        "{%0,%1,%2,%3}, {%4,%5,%6,%7}, {%8,%9}, {%0,%1,%2,%3};\n"
        : "+f"(c[0]), "+f"(c[1]), "+f"(c[2]), "+f"(c[3])
        : "r"(a[0]), "r"(a[1]), "r"(a[2]), "r"(a[3]), "r"(b0), "r"(b1));
}

// ---------------- kernel 1: i2h_seq (fp16 MMA) ----------------
#define X2 72   // half stride; word stride 36, 36%32==4 -> conflict-free

__global__ void __launch_bounds__(256, 2) k_i2h(
    const float* __restrict__ x, const float* __restrict__ Wi,
    const float* __restrict__ bi, float* __restrict__ out)
{
    extern __shared__ char smraw[];
    float*  bs = (float*)smraw;          // [256]
    __half* xs = (__half*)(bs + 256);    // [64][72]
    __half* ws = xs + 64 * X2;           // [256][72]

    const int tid = threadIdx.x;
    const long rb = (long)blockIdx.x * 64;

    for (int i = tid; i < 64 * 64; i += 256) {
        int r = i >> 6, c = i & 63;
        xs[r * X2 + c] = __float2half_rn(x[(rb + r) * 64 + c]);
    }
    for (int i = tid; i < 256 * 64; i += 256) {
        int r = i >> 6, c = i & 63;
        ws[r * X2 + c] = __float2half_rn(Wi[i]);
    }
    bs[tid] = bi[tid];
    __syncthreads();

    const int wid = tid >> 5, lane = tid & 31;
    const int g = lane >> 2, tg = lane & 3;
    const int mg = wid & 1, ng = wid >> 1;

    float acc[2][8][4];
#pragma unroll
    for (int a = 0; a < 2; a++)
#pragma unroll
        for (int b = 0; b < 8; b++)
#pragma unroll
            for (int c = 0; c < 4; c++) acc[a][b][c] = 0.f;

#pragma unroll
    for (int k0 = 0; k0 < 64; k0 += 16) {
        uint32_t af[2][4];
#pragma unroll
        for (int mt = 0; mt < 2; mt++) {
            const __half* p0 = xs + (mg * 32 + mt * 16 + g) * X2 + k0;
            const __half* p1 = p0 + 8 * X2;
            af[mt][0] = ((const uint32_t*)p0)[tg];
            af[mt][1] = ((const uint32_t*)p1)[tg];
            af[mt][2] = ((const uint32_t*)p0)[tg + 4];
            af[mt][3] = ((const uint32_t*)p1)[tg + 4];
        }
#pragma unroll
        for (int nt = 0; nt < 8; nt++) {
            const __half* q = ws + (ng * 64 + nt * 8 + g) * X2 + k0;
            uint32_t b0 = ((const uint32_t*)q)[tg];
            uint32_t b1 = ((const uint32_t*)q)[tg + 4];
            mma16(acc[0][nt], af[0], b0, b1);
            mma16(acc[1][nt], af[1], b0, b1);
        }
    }

#pragma unroll
    for (int mt = 0; mt < 2; mt++)
#pragma unroll
        for (int nt = 0; nt < 8; nt++) {
            int lr = mg * 32 + mt * 16 + g;
            int lc = ng * 64 + nt * 8 + 2 * tg;
            *(float2*)(out + O_I2H + (rb + lr) * 256 + lc) =
                make_float2(acc[mt][nt][0] + bs[lc], acc[mt][nt][1] + bs[lc + 1]);
            *(float2*)(out + O_I2H + (rb + lr + 8) * 256 + lc) =
                make_float2(acc[mt][nt][2] + bs[lc], acc[mt][nt][3] + bs[lc + 1]);
        }
}

// ---------------- kernel 2: recurrence + head (W resident) ----------------
#define HS2 264   // half stride; word stride 132, 132%32==4 -> conflict-free
#define O1S 65

__global__ void __launch_bounds__(256, 1) k_rnn(
    const float* __restrict__ hc1,  const float* __restrict__ Wh2h,
    const float* __restrict__ bh2h, const float* __restrict__ Wh2o,
    const float* __restrict__ bh2o, const float* __restrict__ Wfcc,
    const float* __restrict__ bfcc, float* __restrict__ out)
{
    extern __shared__ char smraw[];
    float*  o1 = (float*)smraw;          // [64][65]
    float*  bh = o1 + 64 * O1S;          // [256]
    float*  bo = bh + 256;               // [64]
    float*  wf = bo + 64;                // [512]
    float*  bf = wf + 512;               // [8]
    __half* Wh = (__half*)(bf + 8);      // [256][264]  W_h2h
    __half* hs = Wh + 256 * HS2;         // [64][264]   h state (fp16)
    __half* wo = hs + 64 * HS2;          // [64][264]   W_h2o

    const int  tid = threadIdx.x;
    const long rb  = (long)blockIdx.x * 64;

    for (int i = tid; i < 256 * 256; i += 256) {
        int r = i >> 8, c = i & 255;
        Wh[r * HS2 + c] = __float2half_rn(Wh2h[i]);
    }
    for (int i = tid; i < 64 * 256; i += 256) {
        int r = i >> 8, c = i & 255;
        hs[r * HS2 + c] = __float2half_rn(hc1[(rb + r) * 256 + c]);
        wo[r * HS2 + c] = __float2half_rn(Wh2o[i]);
    }
    bh[tid] = bh2h[tid];
    if (tid < 64)  bo[tid] = bh2o[tid];
    if (tid < 8)   bf[tid] = bfcc[tid];
    for (int i = tid; i < 512; i += 256) wf[i] = Wfcc[i];
    __syncthreads();

    const int wid = tid >> 5, lane = tid & 31;
    const int g = lane >> 2, tg = lane & 3;
    const int mg = wid & 1, ng = wid >> 1;

    for (int t = 0; t < T_STEPS; t++) {
        // ---- h2h GEMM: [64,256] = hs[64,256] @ Wh^T, K=256 ----
        float acc[2][8][4];
#pragma unroll
        for (int a = 0; a < 2; a++)
#pragma unroll
            for (int b = 0; b < 8; b++)
#pragma unroll
                for (int c = 0; c < 4; c++) acc[a][b][c] = 0.f;

#pragma unroll
        for (int k0 = 0; k0 < 256; k0 += 16) {
            uint32_t af[2][4];
#pragma unroll
            for (int mt = 0; mt < 2; mt++) {
                const __half* p0 = hs + (mg * 32 + mt * 16 + g) * HS2 + k0;
                const __half* p1 = p0 + 8 * HS2;
                af[mt][0] = ((const uint32_t*)p0)[tg];
                af[mt][1] = ((const uint32_t*)p1)[tg];
                af[mt][2] = ((const uint32_t*)p0)[tg + 4];
                af[mt][3] = ((const uint32_t*)p1)[tg + 4];
            }
#pragma unroll
            for (int nt = 0; nt < 8; nt++) {
                const __half* q = Wh + (ng * 64 + nt * 8 + g) * HS2 + k0;
                uint32_t b0 = ((const uint32_t*)q)[tg];
                uint32_t b1 = ((const uint32_t*)q)[tg + 4];
                mma16(acc[0][nt], af[0], b0, b1);
                mma16(acc[1][nt], af[1], b0, b1);
            }
        }

        // ---- epilogue: h2h_seq write, i2h read, tanh -> new h ----
        const size_t tb = (size_t)t * BATCH;
#pragma unroll
        for (int mt = 0; mt < 2; mt++)
#pragma unroll
            for (int nt = 0; nt < 8; nt++) {
                int lr = mg * 32 + mt * 16 + g;
                int lc = ng * 64 + nt * 8 + 2 * tg;
                size_t idx0 = (tb + rb + lr) * 256 + lc;
                size_t idx1 = idx0 + 8 * 256;
                float h0 = acc[mt][nt][0] + bh[lc];
                float h1 = acc[mt][nt][1] + bh[lc + 1];
                float h2 = acc[mt][nt][2] + bh[lc];
                float h3 = acc[mt][nt][3] + bh[lc + 1];
                *(float2*)(out + O_H2H + idx0) = make_float2(h0, h1);
                *(float2*)(out + O_H2H + idx1) = make_float2(h2, h3);
                float2 i0 = *(const float2*)(out + O_I2H + idx0);
                float2 i1 = *(const float2*)(out + O_I2H + idx1);
                float t0 = my_tanh(h0 + i0.x), t1 = my_tanh(h1 + i0.y);
                float t2 = my_tanh(h2 + i1.x), t3 = my_tanh(h3 + i1.y);
                *(__half2*)(hs + lr * HS2 + lc)       = __floats2half2_rn(t0, t1);
                *(__half2*)(hs + (lr + 8) * HS2 + lc) = __floats2half2_rn(t2, t3);
                if (t == T_STEPS - 1) {   // hc1_final in full fp32
                    *(float2*)(out + O_HC1F + (rb + lr) * 256 + lc)     = make_float2(t0, t1);
                    *(float2*)(out + O_HC1F + (rb + lr + 8) * 256 + lc) = make_float2(t2, t3);
                }
            }
        __syncthreads();

        // ---- head GEMM: [64,64] = hs @ wo^T, K=256; warps 2(m) x 4(n16) ----
        float ha[2][2][4];
#pragma unroll
        for (int a = 0; a < 2; a++)
#pragma unroll
            for (int b = 0; b < 2; b++)
#pragma unroll
                for (int c = 0; c < 4; c++) ha[a][b][c] = 0.f;
#pragma unroll
        for (int k0 = 0; k0 < 256; k0 += 16) {
            uint32_t af[2][4];
#pragma unroll
            for (int mt = 0; mt < 2; mt++) {
                const __half* p0 = hs + (mg * 32 + mt * 16 + g) * HS2 + k0;
                const __half* p1 = p0 + 8 * HS2;
                af[mt][0] = ((const uint32_t*)p0)[tg];
                af[mt][1] = ((const uint32_t*)p1)[tg];
                af[mt][2] = ((const uint32_t*)p0)[tg + 4];
                af[mt][3] = ((const uint32_t*)p1)[tg + 4];
            }
#pragma unroll
            for (int nt = 0; nt < 2; nt++) {
                const __half* q = wo + (ng * 16 + nt * 8 + g) * HS2 + k0;
                uint32_t b0 = ((const uint32_t*)q)[tg];
                uint32_t b1 = ((const uint32_t*)q)[tg + 4];
                mma16(ha[0][nt], af[0], b0, b1);
                mma16(ha[1][nt], af[1], b0, b1);
            }
        }
#pragma unroll
        for (int mt = 0; mt < 2; mt++)
#pragma unroll
            for (int nt = 0; nt < 2; nt++) {
                int lr = mg * 32 + mt * 16 + g;
                int lc = ng * 16 + nt * 8 + 2 * tg;
                o1[lr * O1S + lc]           = my_tanh(ha[mt][nt][0] + bo[lc]);
                o1[lr * O1S + lc + 1]       = my_tanh(ha[mt][nt][1] + bo[lc + 1]);
                o1[(lr + 8) * O1S + lc]     = my_tanh(ha[mt][nt][2] + bo[lc]);
                o1[(lr + 8) * O1S + lc + 1] = my_tanh(ha[mt][nt][3] + bo[lc + 1]);
            }
        __syncthreads();

        // ---- fcc: [64,8] = o1[64,64] @ Wfcc^T + bfcc (SIMT) ----
        {
            int m = tid & 63, cp = tid >> 6;
            float s0 = bf[2 * cp], s1 = bf[2 * cp + 1];
            const float* orow = o1 + m * O1S;
            const float* w0 = wf + (2 * cp) * 64;
            const float* w1 = w0 + 64;
#pragma unroll
            for (int o = 0; o < 64; o++) {
                float v = orow[o];
                s0 = fmaf(v, w0[o], s0);
                s1 = fmaf(v, w1[o], s1);
            }
            float* dst = out + O_OUTSEQ + (tb + rb + m) * 8 + 2 * cp;
            dst[0] = s0;
            dst[1] = s1;
        }
        __syncthreads();   // protect hs (rewritten next step) & o1
    }
}

#define SM_I2H (256 * 4 + (64 + 256) * X2 * 2)
#define SM_RNN ((64 * O1S + 256 + 64 + 512 + 8) * 4 + (256 + 64 + 64) * HS2 * 2)

extern "C" void kernel_launch(void* const* d_in, const int* in_sizes, int n_in,
                              void* d_out, int out_size) {
    const float* x    = (const float*)d_in[0];
    const float* hc1  = (const float*)d_in[2];
    const float* hc2  = (const float*)d_in[3];
    const float* hc3  = (const float*)d_in[4];
    const float* hc4  = (const float*)d_in[5];
    const float* Wi2h = (const float*)d_in[6];
    const float* bi2h = (const float*)d_in[7];
    const float* Wh2h = (const float*)d_in[8];
    const float* bh2h = (const float*)d_in[9];
    const float* Wh2o = (const float*)d_in[10];
    const float* bh2o = (const float*)d_in[11];
    const float* Wfcc = (const float*)d_in[12];
    const float* bfcc = (const float*)d_in[13];
    float* out = (float*)d_out;

    cudaFuncSetAttribute(k_i2h, cudaFuncAttributeMaxDynamicSharedMemorySize, SM_I2H);
    cudaFuncSetAttribute(k_rnn, cudaFuncAttributeMaxDynamicSharedMemorySize, SM_RNN);

    k_i2h<<<(T_STEPS * BATCH) / 64, 256, SM_I2H>>>(x, Wi2h, bi2h, out);
    k_rnn<<<BATCH / 64, 256, SM_RNN>>>(hc1, Wh2h, bh2h, Wh2o, bh2o, Wfcc, bfcc, out);

    size_t hb = (size_t)BATCH * 256 * sizeof(float);
    cudaMemcpyAsync(out + O_HC2, hc2, hb, cudaMemcpyDeviceToDevice, 0);
    cudaMemcpyAsync(out + O_HC3, hc3, hb, cudaMemcpyDeviceToDevice, 0);
    cudaMemcpyAsync(out + O_HC4, hc4, hb, cudaMemcpyDeviceToDevice, 0);
}

// round 6
// speedup vs baseline: 1.8699x; 1.4372x over previous
#include <cuda_runtime.h>
#include <cuda_fp16.h>
#include <cuda_bf16.h>
#include <stdint.h>

#define T_STEPS 16
#define BATCH   8192

// Output offsets (floats): output_seq, hc1_final, hc2, hc3, hc4, i2h_seq, h2h_seq
#define O_OUTSEQ 0ul
#define O_HC1F   1048576ul
#define O_HC2    3145728ul
#define O_HC3    5242880ul
#define O_HC4    7340032ul
#define O_I2H    9437184ul
#define O_H2H    42991616ul

// fp16 scratch (pre-converted weights/activations)
__device__ __half g_xh[8388608];    // x   [16,8192,64]
__device__ __half g_wih[16384];     // W_i2h [256,64]
__device__ __half g_whh[65536];     // W_h2h [256,256]
__device__ __half g_woh[16384];     // W_h2o [64,256]

__device__ __forceinline__ float my_tanh(float x) {
    float e = __expf(2.f * x);
    return 1.f - __fdividef(2.f, e + 1.f);
}
__device__ __forceinline__ void mma16(float c[4], const uint32_t a[4],
                                      uint32_t b0, uint32_t b1) {
    asm volatile(
        "mma.sync.aligned.m16n8k16.row.col.f32.f16.f16.f32 "
        "{%0,%1,%2,%3}, {%4,%5,%6,%7}, {%8,%9}, {%0,%1,%2,%3};\n"
        : "+f"(c[0]), "+f"(c[1]), "+f"(c[2]), "+f"(c[3])
        : "r"(a[0]), "r"(a[1]), "r"(a[2]), "r"(a[3]), "r"(b0), "r"(b1));
}
__device__ __forceinline__ void cpa16(uint32_t dst, const void* src) {
    asm volatile("cp.async.cg.shared.global [%0], [%1], 16;" :: "r"(dst), "l"(src) : "memory");
}

// ---------------- kernel 0: fp32 -> fp16 prepass ----------------
// regions: x[0,8388608) wi[..8404992) wh[..8470528) wo[..8486912)
__global__ void k_prep(const float* __restrict__ x,  const float* __restrict__ wi,
                       const float* __restrict__ wh, const float* __restrict__ wo)
{
    long i = (long)(blockIdx.x * 256 + threadIdx.x) * 8;
    const float* src; __half* dst; long off;
    if (i < 8388608)      { src = x;  dst = g_xh;  off = i; }
    else if (i < 8404992) { src = wi; dst = g_wih; off = i - 8388608; }
    else if (i < 8470528) { src = wh; dst = g_whh; off = i - 8404992; }
    else                  { src = wo; dst = g_woh; off = i - 8470528; }
    float4 a = *(const float4*)(src + off);
    float4 b = *(const float4*)(src + off + 4);
    union { __half2 h[4]; uint4 u; } cv;
    cv.h[0] = __floats2half2_rn(a.x, a.y);
    cv.h[1] = __floats2half2_rn(a.z, a.w);
    cv.h[2] = __floats2half2_rn(b.x, b.y);
    cv.h[3] = __floats2half2_rn(b.z, b.w);
    *(uint4*)(dst + off) = cv.u;
}

// ---------------- kernel 1: i2h_seq (fp16 MMA, cp.async feed) ----------------
#define X2 72   // half stride; word stride 36, 36%32==4 -> conflict-free

__global__ void __launch_bounds__(256, 2) k_i2h(
    const float* __restrict__ bi, float* __restrict__ out)
{
    extern __shared__ char smraw[];
    float*  bs = (float*)smraw;          // [256]
    __half* xs = (__half*)(bs + 256);    // [64][72]
    __half* ws = xs + 64 * X2;           // [256][72]

    const int tid = threadIdx.x;
    const long rb = (long)blockIdx.x * 64;
    const uint32_t base = (uint32_t)__cvta_generic_to_shared(smraw);
    const uint32_t xs_s = base + 1024;
    const uint32_t ws_s = xs_s + 64 * X2 * 2;

    for (int ch = tid; ch < 512; ch += 256) {          // x tile: 64 rows x 8 chunks
        int r = ch >> 3, c8 = ch & 7;
        cpa16(xs_s + r * 144 + c8 * 16, g_xh + (rb + r) * 64 + c8 * 8);
    }
    for (int ch = tid; ch < 2048; ch += 256) {         // W: 256 rows x 8 chunks
        int r = ch >> 3, c8 = ch & 7;
        cpa16(ws_s + r * 144 + c8 * 16, g_wih + r * 64 + c8 * 8);
    }
    bs[tid] = bi[tid];
    asm volatile("cp.async.commit_group;\ncp.async.wait_group 0;" ::: "memory");
    __syncthreads();

    const int wid = tid >> 5, lane = tid & 31;
    const int g = lane >> 2, tg = lane & 3;
    const int mg = wid & 1, ng = wid >> 1;

    float acc[2][8][4];
#pragma unroll
    for (int a = 0; a < 2; a++)
#pragma unroll
        for (int b = 0; b < 8; b++)
#pragma unroll
            for (int c = 0; c < 4; c++) acc[a][b][c] = 0.f;

#pragma unroll
    for (int k0 = 0; k0 < 64; k0 += 16) {
        uint32_t af[2][4];
#pragma unroll
        for (int mt = 0; mt < 2; mt++) {
            const __half* p0 = xs + (mg * 32 + mt * 16 + g) * X2 + k0;
            const __half* p1 = p0 + 8 * X2;
            af[mt][0] = ((const uint32_t*)p0)[tg];
            af[mt][1] = ((const uint32_t*)p1)[tg];
            af[mt][2] = ((const uint32_t*)p0)[tg + 4];
            af[mt][3] = ((const uint32_t*)p1)[tg + 4];
        }
#pragma unroll
        for (int nt = 0; nt < 8; nt++) {
            const __half* q = ws + (ng * 64 + nt * 8 + g) * X2 + k0;
            uint32_t b0 = ((const uint32_t*)q)[tg];
            uint32_t b1 = ((const uint32_t*)q)[tg + 4];
            mma16(acc[0][nt], af[0], b0, b1);
            mma16(acc[1][nt], af[1], b0, b1);
        }
    }

#pragma unroll
    for (int mt = 0; mt < 2; mt++)
#pragma unroll
        for (int nt = 0; nt < 8; nt++) {
            int lr = mg * 32 + mt * 16 + g;
            int lc = ng * 64 + nt * 8 + 2 * tg;
            *(float2*)(out + O_I2H + (rb + lr) * 256 + lc) =
                make_float2(acc[mt][nt][0] + bs[lc], acc[mt][nt][1] + bs[lc + 1]);
            *(float2*)(out + O_I2H + (rb + lr + 8) * 256 + lc) =
                make_float2(acc[mt][nt][2] + bs[lc], acc[mt][nt][3] + bs[lc + 1]);
        }
}

// ---------------- kernel 2: recurrence + head (512 threads) ----------------
#define HS2 264   // half stride; word stride 132, 132%32==4 -> conflict-free
#define O1S 65

__global__ void __launch_bounds__(512, 1) k_rnn(
    const float* __restrict__ hc1,  const float* __restrict__ bh2h,
    const float* __restrict__ bh2o, const float* __restrict__ Wfcc,
    const float* __restrict__ bfcc, float* __restrict__ out)
{
    extern __shared__ char smraw[];
    float*  o1 = (float*)smraw;          // [64][65]
    float*  bh = o1 + 64 * O1S;          // [256]
    float*  bo = bh + 256;               // [64]
    float*  wf = bo + 64;                // [512]
    float*  bf = wf + 512;               // [8]     -> 5000 floats = 20000 B
    __half* Wh = (__half*)(bf + 8);      // [256][264]
    __half* hs = Wh + 256 * HS2;         // [64][264]
    __half* wo = hs + 64 * HS2;          // [64][264]

    const int  tid = threadIdx.x;
    const long rb  = (long)blockIdx.x * 64;
    const uint32_t base = (uint32_t)__cvta_generic_to_shared(smraw);
    const uint32_t wh_s = base + 20000;
    const uint32_t wo_s = wh_s + 320 * 528;   // (256+64)*HS2 halves

    for (int ch = tid; ch < 8192; ch += 512) {    // Wh: 256 rows x 32 chunks
        int r = ch >> 5, c8 = ch & 31;
        cpa16(wh_s + r * 528 + c8 * 16, g_whh + r * 256 + c8 * 8);
    }
    for (int ch = tid; ch < 2048; ch += 512) {    // wo: 64 rows x 32 chunks
        int r = ch >> 5, c8 = ch & 31;
        cpa16(wo_s + r * 528 + c8 * 16, g_woh + r * 256 + c8 * 8);
    }
    asm volatile("cp.async.commit_group;" ::: "memory");

    for (int i = tid; i < 64 * 256; i += 512) {   // h state fp32 -> fp16
        int r = i >> 8, c = i & 255;
        hs[r * HS2 + c] = __float2half_rn(hc1[(rb + r) * 256 + c]);
    }
    if (tid < 256) bh[tid] = bh2h[tid];
    if (tid < 64)  bo[tid] = bh2o[tid];
    if (tid < 8)   bf[tid] = bfcc[tid];
    wf[tid] = Wfcc[tid];   // 512 elems, one per thread
    asm volatile("cp.async.wait_group 0;" ::: "memory");
    __syncthreads();

    const int wid = tid >> 5, lane = tid & 31;
    const int g = lane >> 2, tg = lane & 3;
    const int mg = wid & 1, ng = wid >> 1;   // 2 M-halves x 8 N-groups(32)

    for (int t = 0; t < T_STEPS; t++) {
        // ---- h2h GEMM: [64,256] = hs @ Wh^T, K=256 ----
        float acc[2][4][4];
#pragma unroll
        for (int a = 0; a < 2; a++)
#pragma unroll
            for (int b = 0; b < 4; b++)
#pragma unroll
                for (int c = 0; c < 4; c++) acc[a][b][c] = 0.f;

#pragma unroll
        for (int k0 = 0; k0 < 256; k0 += 16) {
            uint32_t af[2][4];
#pragma unroll
            for (int mt = 0; mt < 2; mt++) {
                const __half* p0 = hs + (mg * 32 + mt * 16 + g) * HS2 + k0;
                const __half* p1 = p0 + 8 * HS2;
                af[mt][0] = ((const uint32_t*)p0)[tg];
                af[mt][1] = ((const uint32_t*)p1)[tg];
                af[mt][2] = ((const uint32_t*)p0)[tg + 4];
                af[mt][3] = ((const uint32_t*)p1)[tg + 4];
            }
#pragma unroll
            for (int nt = 0; nt < 4; nt++) {
                const __half* q = Wh + (ng * 32 + nt * 8 + g) * HS2 + k0;
                uint32_t b0 = ((const uint32_t*)q)[tg];
                uint32_t b1 = ((const uint32_t*)q)[tg + 4];
                mma16(acc[0][nt], af[0], b0, b1);
                mma16(acc[1][nt], af[1], b0, b1);
            }
        }
        __syncthreads();   // all warps done READING hs before epilogue rewrites it

        // ---- epilogue: h2h_seq write, i2h read, tanh -> new h ----
        const size_t tb = (size_t)t * BATCH;
#pragma unroll
        for (int mt = 0; mt < 2; mt++)
#pragma unroll
            for (int nt = 0; nt < 4; nt++) {
                int lr = mg * 32 + mt * 16 + g;
                int lc = ng * 32 + nt * 8 + 2 * tg;
                size_t idx0 = (tb + rb + lr) * 256 + lc;
                size_t idx1 = idx0 + 8 * 256;
                float h0 = acc[mt][nt][0] + bh[lc];
                float h1 = acc[mt][nt][1] + bh[lc + 1];
                float h2 = acc[mt][nt][2] + bh[lc];
                float h3 = acc[mt][nt][3] + bh[lc + 1];
                *(float2*)(out + O_H2H + idx0) = make_float2(h0, h1);
                *(float2*)(out + O_H2H + idx1) = make_float2(h2, h3);
                float2 i0 = *(const float2*)(out + O_I2H + idx0);
                float2 i1 = *(const float2*)(out + O_I2H + idx1);
                float t0 = my_tanh(h0 + i0.x), t1 = my_tanh(h1 + i0.y);
                float t2 = my_tanh(h2 + i1.x), t3 = my_tanh(h3 + i1.y);
                *(__half2*)(hs + lr * HS2 + lc)       = __floats2half2_rn(t0, t1);
                *(__half2*)(hs + (lr + 8) * HS2 + lc) = __floats2half2_rn(t2, t3);
                if (t == T_STEPS - 1) {   // hc1_final in full fp32
                    *(float2*)(out + O_HC1F + (rb + lr) * 256 + lc)     = make_float2(t0, t1);
                    *(float2*)(out + O_HC1F + (rb + lr + 8) * 256 + lc) = make_float2(t2, t3);
                }
            }
        __syncthreads();

        // ---- head GEMM: [64,64] = hs @ wo^T, K=256; 2(M) x 8(N of 8) ----
        float ha[2][4];
#pragma unroll
        for (int a = 0; a < 2; a++)
#pragma unroll
            for (int c = 0; c < 4; c++) ha[a][c] = 0.f;
#pragma unroll
        for (int k0 = 0; k0 < 256; k0 += 16) {
            uint32_t af[2][4];
#pragma unroll
            for (int mt = 0; mt < 2; mt++) {
                const __half* p0 = hs + (mg * 32 + mt * 16 + g) * HS2 + k0;
                const __half* p1 = p0 + 8 * HS2;
                af[mt][0] = ((const uint32_t*)p0)[tg];
                af[mt][1] = ((const uint32_t*)p1)[tg];
                af[mt][2] = ((const uint32_t*)p0)[tg + 4];
                af[mt][3] = ((const uint32_t*)p1)[tg + 4];
            }
            const __half* q = wo + (ng * 8 + g) * HS2 + k0;
            uint32_t b0 = ((const uint32_t*)q)[tg];
            uint32_t b1 = ((const uint32_t*)q)[tg + 4];
            mma16(ha[0], af[0], b0, b1);
            mma16(ha[1], af[1], b0, b1);
        }
#pragma unroll
        for (int mt = 0; mt < 2; mt++) {
            int lr = mg * 32 + mt * 16 + g;
            int lc = ng * 8 + 2 * tg;
            o1[lr * O1S + lc]           = my_tanh(ha[mt][0] + bo[lc]);
            o1[lr * O1S + lc + 1]       = my_tanh(ha[mt][1] + bo[lc + 1]);
            o1[(lr + 8) * O1S + lc]     = my_tanh(ha[mt][2] + bo[lc]);
            o1[(lr + 8) * O1S + lc + 1] = my_tanh(ha[mt][3] + bo[lc + 1]);
        }
        __syncthreads();

        // ---- fcc: [64,8] = o1 @ Wfcc^T + bfcc; one output/thread ----
        {
            int m = tid & 63, cp = tid >> 6;   // cp 0..7
            float s = bf[cp];
            const float* orow = o1 + m * O1S;
            const float* w = wf + cp * 64;
#pragma unroll
            for (int o = 0; o < 64; o++) s = fmaf(orow[o], w[o], s);
            out[O_OUTSEQ + (tb + rb + m) * 8 + cp] = s;
        }
        // no barrier needed here: next GEMM only reads hs; the next epilogue's
        // hs/o1 writes are fenced by next iteration's first __syncthreads.
    }
}

#define SM_I2H (256 * 4 + (64 + 256) * X2 * 2)
#define SM_RNN ((64 * O1S + 256 + 64 + 512 + 8) * 4 + (256 + 64 + 64) * HS2 * 2)

extern "C" void kernel_launch(void* const* d_in, const int* in_sizes, int n_in,
                              void* d_out, int out_size) {
    const float* x    = (const float*)d_in[0];
    const float* hc1  = (const float*)d_in[2];
    const float* hc2  = (const float*)d_in[3];
    const float* hc3  = (const float*)d_in[4];
    const float* hc4  = (const float*)d_in[5];
    const float* Wi2h = (const float*)d_in[6];
    const float* bi2h = (const float*)d_in[7];
    const float* Wh2h = (const float*)d_in[8];
    const float* bh2h = (const float*)d_in[9];
    const float* Wh2o = (const float*)d_in[10];
    const float* bh2o = (const float*)d_in[11];
    const float* Wfcc = (const float*)d_in[12];
    const float* bfcc = (const float*)d_in[13];
    float* out = (float*)d_out;

    cudaFuncSetAttribute(k_i2h, cudaFuncAttributeMaxDynamicSharedMemorySize, SM_I2H);
    cudaFuncSetAttribute(k_rnn, cudaFuncAttributeMaxDynamicSharedMemorySize, SM_RNN);

    k_prep<<<4144, 256>>>(x, Wi2h, Wh2h, Wh2o);
    k_i2h<<<(T_STEPS * BATCH) / 64, 256, SM_I2H>>>(bi2h, out);
    k_rnn<<<BATCH / 64, 512, SM_RNN>>>(hc1, bh2h, bh2o, Wfcc, bfcc, out);

    size_t hb = (size_t)BATCH * 256 * sizeof(float);
    cudaMemcpyAsync(out + O_HC2, hc2, hb, cudaMemcpyDeviceToDevice, 0);
    cudaMemcpyAsync(out + O_HC3, hc3, hb, cudaMemcpyDeviceToDevice, 0);
    cudaMemcpyAsync(out + O_HC4, hc4, hb, cudaMemcpyDeviceToDevice, 0);
}